// round 2
// baseline (speedup 1.0000x reference)
#include <cuda_runtime.h>
#include <cstdint>

// Problem constants (fixed by the reference)
#define DD 8
#define BB 8
#define NN 2048

// 64-bit spike mask per presynaptic neuron e: bit (d*8 + b) set iff Xd[d,b,e] == 1
__device__ unsigned long long g_spike[NN];

// ---------------------------------------------------------------------------
// Kernel 1: zero output + spike masks (d_out is poisoned by the harness)
// ---------------------------------------------------------------------------
__global__ void zero_kernel(float* __restrict__ out) {
    int i = blockIdx.x * blockDim.x + threadIdx.x;
    if (i < BB * NN) out[i] = 0.0f;
    if (i < NN) g_spike[i] = 0ull;
}

// ---------------------------------------------------------------------------
// Kernel 2: pack Xd (D,B,N) binary floats into per-e 64-bit masks
// ---------------------------------------------------------------------------
__global__ void pack_kernel(const float* __restrict__ Xd) {
    int i = blockIdx.x * blockDim.x + threadIdx.x;  // over D*B*N
    if (i >= DD * BB * NN) return;
    if (Xd[i] > 0.5f) {
        int e  = i % NN;
        int db = i / NN;             // d*B + b  -> bit index
        atomicOr(&g_spike[e], 1ull << db);
    }
}

// ---------------------------------------------------------------------------
// Kernel 3: fused gather + blend + reduce
//   grid: (N/256, ESPLIT), block: 256 threads. thread -> one output column o,
//   block.y -> a chunk of presynaptic e. Per-batch partials in registers,
//   atomicAdd into out at the end.
// ---------------------------------------------------------------------------
#define ESPLIT 32
#define ECHUNK (NN / ESPLIT)   // 64

__global__ void __launch_bounds__(256, 4)
delta_syn_kernel(const float* __restrict__ dm,    // delaymap (D,N,N)
                 const float* __restrict__ W,     // (N,N)
                 const float* __restrict__ Wl,    // Wlong (B,N,N)
                 const float* __restrict__ F,     // STDP_frac (N,N)
                 const float* __restrict__ S,     // signs (N,N)
                 float* __restrict__ out)         // (B,N)
{
    const int o     = blockIdx.x * blockDim.x + threadIdx.x;  // output neuron
    const int ebase = blockIdx.y * ECHUNK;

    float acc[BB];
#pragma unroll
    for (int b = 0; b < BB; b++) acc[b] = 0.0f;

    for (int ee = 0; ee < ECHUNK; ee++) {
        const int e = ebase + ee;
        const unsigned long long bits = g_spike[e];  // warp-uniform
        if (bits == 0ull) continue;                  // no spikes anywhere for e

        // Load one-hot delay column for this synapse (e -> o): 8 coalesced streams
        const float* dmp = dm + (size_t)e * NN + o;
        float d0 = dmp[0 * (size_t)NN * NN];
        float d1 = dmp[1 * (size_t)NN * NN];
        float d2 = dmp[2 * (size_t)NN * NN];
        float d3 = dmp[3 * (size_t)NN * NN];
        float d4 = dmp[4 * (size_t)NN * NN];
        float d5 = dmp[5 * (size_t)NN * NN];
        float d6 = dmp[6 * (size_t)NN * NN];
        float d7 = dmp[7 * (size_t)NN * NN];

        // One-hot -> index via dot product with [0..7] (exact small integers)
        float fidx = d1;
        fidx = fmaf(d2, 2.0f, fidx);
        fidx = fmaf(d3, 3.0f, fidx);
        fidx = fmaf(d4, 4.0f, fidx);
        fidx = fmaf(d5, 5.0f, fidx);
        fidx = fmaf(d6, 6.0f, fidx);
        fidx = fmaf(d7, 7.0f, fidx);
        const int didx = (int)fidx;
        (void)d0;  // d0 contributes index 0

        // 8-bit gate over batches for this synapse's delay
        const unsigned gb = (unsigned)(bits >> (didx * BB)) & 0xFFu;
        if (gb == 0) continue;

        // Static coefficients (needed for ~96% of active lanes; load once)
        const size_t eo = (size_t)e * NN + o;
        const float s = S[eo];
        const float w = W[eo];
        const float f = F[eo];
        const float cs = s * w * (1.0f - f);  // static part
        const float cp = s * f;               // plastic multiplier

        const float* wlp = Wl + eo;
#pragma unroll
        for (int b = 0; b < BB; b++) {
            if (gb & (1u << b)) {
                acc[b] += cs + cp * wlp[(size_t)b * NN * NN];
            }
        }
    }

#pragma unroll
    for (int b = 0; b < BB; b++) {
        atomicAdd(&out[b * NN + o], acc[b]);
    }
}

// ---------------------------------------------------------------------------
// Launch
// ---------------------------------------------------------------------------
extern "C" void kernel_launch(void* const* d_in, const int* in_sizes, int n_in,
                              void* d_out, int out_size) {
    const float* Xd = (const float*)d_in[0];   // (D,B,N)
    const float* dm = (const float*)d_in[1];   // (D,N,N)
    const float* W  = (const float*)d_in[2];   // (N,N)
    const float* Wl = (const float*)d_in[3];   // (B,N,N)
    const float* F  = (const float*)d_in[4];   // (N,N)
    const float* S  = (const float*)d_in[5];   // (N,N)
    float* out = (float*)d_out;                // (B,N)

    zero_kernel<<<(BB * NN + 255) / 256, 256>>>(out);
    pack_kernel<<<(DD * BB * NN + 255) / 256, 256>>>(Xd);

    dim3 grid(NN / 256, ESPLIT);
    delta_syn_kernel<<<grid, 256>>>(dm, W, Wl, F, S, out);
}

// round 3
// speedup vs baseline: 2.0068x; 2.0068x over previous
#include <cuda_runtime.h>
#include <cstdint>

#define DD 8
#define BB 8
#define NN 2048
#define NN2 (NN * NN)        // 4194304
#define NQ  (NN2 / 4)        // 1048576 quads

// 64-bit spike mask per presynaptic neuron e: bit (d*8 + b) set iff Xd[d,b,e]==1
__device__ unsigned long long g_spike[NN];
// Gate byte per synapse (e,o): bit b set iff Xd[didx(e,o), b, e]==1. Packed 4/word.
__device__ unsigned int g_gate[NQ];   // 4 MB static scratch (allowed)

// ---------------------------------------------------------------------------
// Kernel 1: zero output + spike masks
// ---------------------------------------------------------------------------
__global__ void zero_kernel(float* __restrict__ out) {
    int i = blockIdx.x * blockDim.x + threadIdx.x;
    if (i < BB * NN) out[i] = 0.0f;
    if (i < NN) g_spike[i] = 0ull;
}

// ---------------------------------------------------------------------------
// Kernel 2: pack Xd (D,B,N) binary floats into per-e 64-bit masks
// ---------------------------------------------------------------------------
__global__ void pack_kernel(const float* __restrict__ Xd) {
    int i = blockIdx.x * blockDim.x + threadIdx.x;  // over D*B*N
    if (i >= DD * BB * NN) return;
    if (Xd[i] > 0.5f) {
        int e  = i % NN;
        int db = i / NN;             // bit index = d*B + b
        atomicOr(&g_spike[e], 1ull << db);
    }
}

// ---------------------------------------------------------------------------
// Kernel 3 (A): stream delaymap -> gate bytes.
//   One thread per 4 consecutive o. didx via one-hot dot product (d=0 stream
//   is never read: it contributes 0). Pure streaming, 4096 CTAs.
// ---------------------------------------------------------------------------
__global__ void __launch_bounds__(256)
gate_kernel(const float4* __restrict__ dm4) {
    int i = blockIdx.x * blockDim.x + threadIdx.x;  // quad index over N*N/4
    if (i >= NQ) return;
    const int e = i / (NN / 4);                     // warp-uniform row

    float fx = 0.f, fy = 0.f, fz = 0.f, fw = 0.f;
#pragma unroll
    for (int d = 1; d < DD; d++) {
        float4 v = dm4[(size_t)d * NQ + i];
        const float fd = (float)d;
        fx = fmaf(v.x, fd, fx);
        fy = fmaf(v.y, fd, fy);
        fz = fmaf(v.z, fd, fz);
        fw = fmaf(v.w, fd, fw);
    }
    const unsigned long long bits = g_spike[e];
    unsigned b0 = (unsigned)(bits >> (((int)fx) * 8)) & 0xFFu;
    unsigned b1 = (unsigned)(bits >> (((int)fy) * 8)) & 0xFFu;
    unsigned b2 = (unsigned)(bits >> (((int)fz) * 8)) & 0xFFu;
    unsigned b3 = (unsigned)(bits >> (((int)fw) * 8)) & 0xFFu;
    g_gate[i] = b0 | (b1 << 8) | (b2 << 16) | (b3 << 24);
}

// ---------------------------------------------------------------------------
// Kernel 4 (B): gated blend + reduce.
//   thread -> output neuron o; block.y -> chunk of e. 1024 CTAs.
// ---------------------------------------------------------------------------
#define ESPLIT 128
#define ECHUNK (NN / ESPLIT)   // 16

__global__ void __launch_bounds__(256)
reduce_kernel(const float* __restrict__ W,     // (N,N)
              const float* __restrict__ Wl,    // Wlong (B,N,N)
              const float* __restrict__ F,     // STDP_frac (N,N)
              const float* __restrict__ S,     // signs (N,N)
              float* __restrict__ out)         // (B,N)
{
    const int o     = blockIdx.x * blockDim.x + threadIdx.x;
    const int ebase = blockIdx.y * ECHUNK;
    const unsigned char* __restrict__ gb8 = (const unsigned char*)g_gate;

    float acc[BB];
#pragma unroll
    for (int b = 0; b < BB; b++) acc[b] = 0.0f;

#pragma unroll 4
    for (int ee = 0; ee < ECHUNK; ee++) {
        const int e = ebase + ee;
        const size_t eo = (size_t)e * NN + o;
        const unsigned gb = gb8[eo];
        if (gb == 0) continue;

        const float s = S[eo];
        const float w = W[eo];
        const float f = F[eo];
        const float cs = s * w * (1.0f - f);   // static part
        const float cp = s * f;                // plastic multiplier

        const float* wlp = Wl + eo;
#pragma unroll
        for (int b = 0; b < BB; b++) {
            if (gb & (1u << b)) {
                acc[b] += cs + cp * wlp[(size_t)b * NN2];
            }
        }
    }

#pragma unroll
    for (int b = 0; b < BB; b++) {
        atomicAdd(&out[b * NN + o], acc[b]);
    }
}

// ---------------------------------------------------------------------------
// Launch
// ---------------------------------------------------------------------------
extern "C" void kernel_launch(void* const* d_in, const int* in_sizes, int n_in,
                              void* d_out, int out_size) {
    const float* Xd = (const float*)d_in[0];   // (D,B,N)
    const float* dm = (const float*)d_in[1];   // (D,N,N)
    const float* W  = (const float*)d_in[2];   // (N,N)
    const float* Wl = (const float*)d_in[3];   // (B,N,N)
    const float* F  = (const float*)d_in[4];   // (N,N)
    const float* S  = (const float*)d_in[5];   // (N,N)
    float* out = (float*)d_out;                // (B,N)

    zero_kernel<<<(BB * NN + 255) / 256, 256>>>(out);
    pack_kernel<<<(DD * BB * NN + 255) / 256, 256>>>(Xd);
    gate_kernel<<<NQ / 256, 256>>>((const float4*)dm);

    dim3 grid(NN / 256, ESPLIT);
    reduce_kernel<<<grid, 256>>>(W, Wl, F, S, out);
}